// round 4
// baseline (speedup 1.0000x reference)
#include <cuda_runtime.h>
#include <cuda_bf16.h>
#include <math.h>

#define NB 4096
#define NL 8192
#define NT 256
#define NBLK 1184                  // 8 blocks * 148 SMs

// Per-row partials (value independent of which block computes them -> deterministic).
__device__ float    g_lossR[NB];   // sum(log_term) * inv_len for the row
__device__ int      g_tpR[NB];
__device__ int      g_tnR[NB];
__device__ int      g_gpR[NB];
__device__ unsigned g_ticket = 0;  // dynamic row scheduler
__device__ unsigned g_done   = 0;  // last-block-done counter

__device__ __forceinline__ void acc_elem(float p, float t,
                                         float& lg_sum, int& tp, int& tn, int& gp) {
    p = (p - p == 0.0f) ? p : 0.0f;         // torch.where(isnan|isinf, 0, pred)
    bool tb = (t > 0.0f);                   // truth is exactly 0.0 or 1.0
    float x  = tb ? p : (1.0f - p);
    lg_sum += fmaxf(__logf(x), -100.0f);    // __logf(0) = -inf -> clamp
    bool pb = (p > 0.5f);
    tp += (int)(pb && tb);
    tn += (int)(!pb && !tb);
    gp += (int)tb;
}

__global__ void __launch_bounds__(NT) main_kernel(const float* __restrict__ pred,
                                                  const float* __restrict__ truth,
                                                  const int*   __restrict__ lengths,
                                                  float* __restrict__ out,
                                                  int out_size) {
    __shared__ int   s_row;
    __shared__ float s_l[NT / 32];
    __shared__ int   s_tp[NT / 32], s_tn[NT / 32], s_gp[NT / 32];
    const int wid = threadIdx.x >> 5, lid = threadIdx.x & 31;

    // ---- dynamic row loop ----
    while (true) {
        if (threadIdx.x == 0) s_row = (int)atomicAdd(&g_ticket, 1u);
        __syncthreads();
        const int row = s_row;
        if (row >= NB) break;

        const int len = __ldg(lengths + row);
        float lg = 0.0f;
        int tp = 0, tn = 0, gp = 0;

        const size_t off = (size_t)row * NL;
        const float4* __restrict__ p4 = reinterpret_cast<const float4*>(pred + off);
        const float4* __restrict__ t4 = reinterpret_cast<const float4*>(truth + off);
        const int n4 = len >> 2;
        #pragma unroll 2
        for (int i = threadIdx.x; i < n4; i += NT) {
            float4 p = p4[i];
            float4 t = t4[i];
            acc_elem(p.x, t.x, lg, tp, tn, gp);
            acc_elem(p.y, t.y, lg, tp, tn, gp);
            acc_elem(p.z, t.z, lg, tp, tn, gp);
            acc_elem(p.w, t.w, lg, tp, tn, gp);
        }
        const int base = n4 << 2;
        if ((int)threadIdx.x < len - base)
            acc_elem(pred[off + base + threadIdx.x],
                     truth[off + base + threadIdx.x], lg, tp, tn, gp);

        // block reduce (fixed order -> deterministic per-row value)
        #pragma unroll
        for (int s = 16; s > 0; s >>= 1) {
            lg += __shfl_down_sync(0xffffffffu, lg, s);
            tp += __shfl_down_sync(0xffffffffu, tp, s);
            tn += __shfl_down_sync(0xffffffffu, tn, s);
            gp += __shfl_down_sync(0xffffffffu, gp, s);
        }
        if (lid == 0) { s_l[wid] = lg; s_tp[wid] = tp; s_tn[wid] = tn; s_gp[wid] = gp; }
        __syncthreads();
        if (threadIdx.x == 0) {
            float L = 0.0f; int a = 0, b = 0, c = 0;
            #pragma unroll
            for (int w = 0; w < NT / 32; w++) { L += s_l[w]; a += s_tp[w]; b += s_tn[w]; c += s_gp[w]; }
            g_lossR[row] = (len > 0) ? L * __fdividef(1.0f, (float)len) : 0.0f;
            g_tpR[row] = a; g_tnR[row] = b; g_gpR[row] = c;
        }
        __syncthreads();   // protect shared arrays before next row
    }

    // ---- completion + fused finalize ----
    __shared__ bool isLast;
    if (threadIdx.x == 0) {
        __threadfence();
        unsigned t = atomicAdd(&g_done, 1u);
        isLast = (t == (unsigned)(NBLK - 1));
    }
    __syncthreads();
    if (!isLast) return;
    __threadfence();   // acquire all per-row partials

    float L = 0.0f;
    int Tp = 0, Tn = 0, Gp = 0, Valid = 0;
    for (int r = threadIdx.x; r < NB; r += NT) {   // 16 iterations, fixed order
        L  += g_lossR[r];
        Tp += g_tpR[r]; Tn += g_tnR[r]; Gp += g_gpR[r];
        Valid += __ldg(lengths + r);
    }
    #pragma unroll
    for (int s = 16; s > 0; s >>= 1) {
        L     += __shfl_down_sync(0xffffffffu, L,     s);
        Tp    += __shfl_down_sync(0xffffffffu, Tp,    s);
        Tn    += __shfl_down_sync(0xffffffffu, Tn,    s);
        Gp    += __shfl_down_sync(0xffffffffu, Gp,    s);
        Valid += __shfl_down_sync(0xffffffffu, Valid, s);
    }
    __shared__ float fl[NT / 32];
    __shared__ int   f1[NT / 32], f2[NT / 32], f3[NT / 32], f4[NT / 32];
    if (lid == 0) { fl[wid] = L; f1[wid] = Tp; f2[wid] = Tn; f3[wid] = Gp; f4[wid] = Valid; }
    __syncthreads();
    if (threadIdx.x == 0) {
        float LL = 0.0f; int TP = 0, TN = 0, GP = 0, V = 0;
        #pragma unroll
        for (int w = 0; w < NT / 32; w++) { LL += fl[w]; TP += f1[w]; TN += f2[w]; GP += f3[w]; V += f4[w]; }
        int GN = V - GP;
        if (GP < 1) GP = 1;
        if (GN < 1) GN = 1;
        out[0] = -LL / (float)NB;   // accumulated +log terms; bce = -log
        if (out_size > 1) out[1] = ((float)TP / (float)GP) * ((float)TN / (float)GN);
        g_ticket = 0;               // reset scheduler + counter for next graph replay
        g_done   = 0;
    }
}

extern "C" void kernel_launch(void* const* d_in, const int* in_sizes, int n_in,
                              void* d_out, int out_size) {
    const float* pred    = (const float*)d_in[0];
    const float* truth   = (const float*)d_in[1];
    const int*   lengths = (const int*)d_in[2];
    float* out = (float*)d_out;

    main_kernel<<<NBLK, NT>>>(pred, truth, lengths, out, out_size);
}

// round 5
// speedup vs baseline: 1.2660x; 1.2660x over previous
#include <cuda_runtime.h>
#include <cuda_bf16.h>
#include <math.h>

#define NB 4096
#define NL 8192
#define NT 256

// Per-row partials + completion counter (scratch).
__device__ float    g_lossR[NB];   // sum(log_term)/len for the row (0 for empty rows)
__device__ int      g_tpR[NB];
__device__ int      g_tnR[NB];
__device__ int      g_gpR[NB];
__device__ unsigned g_done = 0;

__device__ __forceinline__ void acc_elem(float p, float t,
                                         float& lg_sum, int& tp, int& tn, int& gp) {
    p = (p - p == 0.0f) ? p : 0.0f;         // torch.where(isnan|isinf, 0, pred)
    bool tb = (t > 0.0f);                   // truth is exactly 0.0 or 1.0
    float x  = tb ? p : (1.0f - p);
    lg_sum += fmaxf(__logf(x), -100.0f);    // __logf(0) = -inf -> clamp
    bool pb = (p > 0.5f);
    tp += (int)(pb && tb);
    tn += (int)(!pb && !tb);
    gp += (int)tb;
}

__global__ void __launch_bounds__(NT) main_kernel(const float* __restrict__ pred,
                                                  const float* __restrict__ truth,
                                                  const int*   __restrict__ lengths,
                                                  float* __restrict__ out,
                                                  int out_size) {
    const int row = blockIdx.x;
    const int len = __ldg(lengths + row);
    const size_t off = (size_t)row * NL;
    const float4* __restrict__ p4 = reinterpret_cast<const float4*>(pred + off);
    const float4* __restrict__ t4 = reinterpret_cast<const float4*>(truth + off);

    float lg = 0.0f;
    int tp = 0, tn = 0, gp = 0;

    const int n4 = len >> 2;
    #pragma unroll 2
    for (int i = threadIdx.x; i < n4; i += NT) {
        float4 p = p4[i];
        float4 t = t4[i];
        acc_elem(p.x, t.x, lg, tp, tn, gp);
        acc_elem(p.y, t.y, lg, tp, tn, gp);
        acc_elem(p.z, t.z, lg, tp, tn, gp);
        acc_elem(p.w, t.w, lg, tp, tn, gp);
    }
    const int base = n4 << 2;
    if ((int)threadIdx.x < len - base)
        acc_elem(pred[off + base + threadIdx.x],
                 truth[off + base + threadIdx.x], lg, tp, tn, gp);

    // ---- block reduce (fixed order -> deterministic) ----
    #pragma unroll
    for (int s = 16; s > 0; s >>= 1) {
        lg += __shfl_down_sync(0xffffffffu, lg, s);
        tp += __shfl_down_sync(0xffffffffu, tp, s);
        tn += __shfl_down_sync(0xffffffffu, tn, s);
        gp += __shfl_down_sync(0xffffffffu, gp, s);
    }
    __shared__ float s_l[NT / 32];
    __shared__ int   s_tp[NT / 32], s_tn[NT / 32], s_gp[NT / 32];
    const int wid = threadIdx.x >> 5, lid = threadIdx.x & 31;
    if (lid == 0) { s_l[wid] = lg; s_tp[wid] = tp; s_tn[wid] = tn; s_gp[wid] = gp; }
    __syncthreads();

    __shared__ bool isLast;
    if (threadIdx.x == 0) {
        float L = 0.0f; int a = 0, b = 0, c = 0;
        #pragma unroll
        for (int w = 0; w < NT / 32; w++) { L += s_l[w]; a += s_tp[w]; b += s_tn[w]; c += s_gp[w]; }
        g_lossR[row] = (len > 0) ? L * __fdividef(1.0f, (float)len) : 0.0f;
        g_tpR[row] = a; g_tnR[row] = b; g_gpR[row] = c;
        __threadfence();
        unsigned t = atomicAdd(&g_done, 1u);
        isLast = (t == (unsigned)(NB - 1));
    }
    __syncthreads();
    if (!isLast) return;
    __threadfence();   // acquire all per-row partials

    // ---- fused finalize (single surviving block; partials L2-hot) ----
    float L = 0.0f;
    int Tp = 0, Tn = 0, Gp = 0, Valid = 0;
    for (int r = threadIdx.x; r < NB; r += NT) {   // 16 iterations, fixed order
        L  += g_lossR[r];
        Tp += g_tpR[r]; Tn += g_tnR[r]; Gp += g_gpR[r];
        Valid += __ldg(lengths + r);
    }
    #pragma unroll
    for (int s = 16; s > 0; s >>= 1) {
        L     += __shfl_down_sync(0xffffffffu, L,     s);
        Tp    += __shfl_down_sync(0xffffffffu, Tp,    s);
        Tn    += __shfl_down_sync(0xffffffffu, Tn,    s);
        Gp    += __shfl_down_sync(0xffffffffu, Gp,    s);
        Valid += __shfl_down_sync(0xffffffffu, Valid, s);
    }
    __shared__ float fl[NT / 32];
    __shared__ int   f1[NT / 32], f2[NT / 32], f3[NT / 32], f4[NT / 32];
    if (lid == 0) { fl[wid] = L; f1[wid] = Tp; f2[wid] = Tn; f3[wid] = Gp; f4[wid] = Valid; }
    __syncthreads();
    if (threadIdx.x == 0) {
        float LL = 0.0f; int TP = 0, TN = 0, GP = 0, V = 0;
        #pragma unroll
        for (int w = 0; w < NT / 32; w++) { LL += fl[w]; TP += f1[w]; TN += f2[w]; GP += f3[w]; V += f4[w]; }
        int GN = V - GP;
        if (GP < 1) GP = 1;
        if (GN < 1) GN = 1;
        out[0] = -LL / (float)NB;   // accumulated +log terms; bce = -log
        if (out_size > 1) out[1] = ((float)TP / (float)GP) * ((float)TN / (float)GN);
        g_done = 0;                 // reset for next graph replay
    }
}

extern "C" void kernel_launch(void* const* d_in, const int* in_sizes, int n_in,
                              void* d_out, int out_size) {
    const float* pred    = (const float*)d_in[0];
    const float* truth   = (const float*)d_in[1];
    const int*   lengths = (const int*)d_in[2];
    float* out = (float*)d_out;

    main_kernel<<<NB, NT>>>(pred, truth, lengths, out, out_size);
}

// round 6
// speedup vs baseline: 1.6295x; 1.2871x over previous
#include <cuda_runtime.h>
#include <cuda_bf16.h>
#include <math.h>

#define NB 4096
#define NL 8192
#define NT 256
#define NCH 2                       // chunks per row
#define CHUNK (NL / NCH)            // 4096 elements
#define GRID (NB * NCH)             // 8192 blocks
#define FXSCALE 16777216.0f         // 2^24 fixed-point scale for loss

// Global accumulators (integer -> order-independent -> deterministic).
__device__ unsigned long long g_loss_fx = 0;   // sum of per-chunk bce/len in 2^-24 units
__device__ int      g_tp_acc = 0;
__device__ int      g_tn_acc = 0;
__device__ int      g_gp_acc = 0;
__device__ int      g_valid  = 0;
__device__ unsigned g_done   = 0;

__device__ __forceinline__ void acc_elem(float p, float t,
                                         float& lg_sum, int& tp, int& tn, int& gp) {
    p = (p - p == 0.0f) ? p : 0.0f;         // torch.where(isnan|isinf, 0, pred)
    bool tb = (t > 0.0f);                   // truth is exactly 0.0 or 1.0
    float x  = tb ? p : (1.0f - p);
    lg_sum += fmaxf(__logf(x), -100.0f);    // __logf(0) = -inf -> clamp
    bool pb = (p > 0.5f);
    tp += (int)(pb && tb);
    tn += (int)(!pb && !tb);
    gp += (int)tb;
}

__global__ void __launch_bounds__(NT) main_kernel(const float* __restrict__ pred,
                                                  const float* __restrict__ truth,
                                                  const int*   __restrict__ lengths,
                                                  float* __restrict__ out,
                                                  int out_size) {
    const int row   = blockIdx.x >> 1;       // NCH == 2
    const int chunk = blockIdx.x & 1;
    const int len   = __ldg(lengths + row);
    const int start = chunk * CHUNK;
    const int v     = min(len - start, CHUNK);   // valid elems in this chunk

    if (v > 0) {
        const size_t off = (size_t)row * NL + start;
        const float4* __restrict__ p4 = reinterpret_cast<const float4*>(pred + off);
        const float4* __restrict__ t4 = reinterpret_cast<const float4*>(truth + off);

        float lg = 0.0f;
        int tp = 0, tn = 0, gp = 0;

        const int n4 = v >> 2;
        #pragma unroll 2
        for (int i = threadIdx.x; i < n4; i += NT) {
            float4 p = p4[i];
            float4 t = t4[i];
            acc_elem(p.x, t.x, lg, tp, tn, gp);
            acc_elem(p.y, t.y, lg, tp, tn, gp);
            acc_elem(p.z, t.z, lg, tp, tn, gp);
            acc_elem(p.w, t.w, lg, tp, tn, gp);
        }
        const int base = n4 << 2;
        if ((int)threadIdx.x < v - base)
            acc_elem(pred[off + base + threadIdx.x],
                     truth[off + base + threadIdx.x], lg, tp, tn, gp);

        // ---- block reduce ----
        #pragma unroll
        for (int s = 16; s > 0; s >>= 1) {
            lg += __shfl_down_sync(0xffffffffu, lg, s);
            tp += __shfl_down_sync(0xffffffffu, tp, s);
            tn += __shfl_down_sync(0xffffffffu, tn, s);
            gp += __shfl_down_sync(0xffffffffu, gp, s);
        }
        __shared__ float s_l[NT / 32];
        __shared__ int   s_tp[NT / 32], s_tn[NT / 32], s_gp[NT / 32];
        const int wid = threadIdx.x >> 5, lid = threadIdx.x & 31;
        if (lid == 0) { s_l[wid] = lg; s_tp[wid] = tp; s_tn[wid] = tn; s_gp[wid] = gp; }
        __syncthreads();
        if (threadIdx.x == 0) {
            float L = 0.0f; int a = 0, b = 0, c = 0;
            #pragma unroll
            for (int w = 0; w < NT / 32; w++) { L += s_l[w]; a += s_tp[w]; b += s_tn[w]; c += s_gp[w]; }
            // chunk contribution to loss: (-sum logs)/len, fixed-point (exact-commutative add)
            float S = -L * __fdividef(1.0f, (float)len);
            atomicAdd(&g_loss_fx, (unsigned long long)__float2ll_rn(S * FXSCALE));
            if (a) atomicAdd(&g_tp_acc, a);
            if (b) atomicAdd(&g_tn_acc, b);
            if (c) atomicAdd(&g_gp_acc, c);
        }
    }

    // ---- completion + O(1) finalize by last-done block's thread 0 ----
    if (threadIdx.x == 0) {
        if (chunk == 0 && len > 0) atomicAdd(&g_valid, len);
        __threadfence();
        unsigned t = atomicAdd(&g_done, 1u);
        if (t == (unsigned)(GRID - 1)) {
            // coherent read-back via atomics (all prior atomics landed in L2)
            unsigned long long fx = atomicAdd(&g_loss_fx, 0ULL);
            int TP = atomicAdd(&g_tp_acc, 0);
            int TN = atomicAdd(&g_tn_acc, 0);
            int GP = atomicAdd(&g_gp_acc, 0);
            int V  = atomicAdd(&g_valid, 0);
            int GN = V - GP;
            if (GP < 1) GP = 1;
            if (GN < 1) GN = 1;
            out[0] = (float)((double)fx / (double)FXSCALE / (double)NB);
            if (out_size > 1) out[1] = ((float)TP / (float)GP) * ((float)TN / (float)GN);
            // reset for next graph replay
            g_loss_fx = 0ULL;
            g_tp_acc = 0; g_tn_acc = 0; g_gp_acc = 0; g_valid = 0;
            g_done = 0;
        }
    }
}

extern "C" void kernel_launch(void* const* d_in, const int* in_sizes, int n_in,
                              void* d_out, int out_size) {
    const float* pred    = (const float*)d_in[0];
    const float* truth   = (const float*)d_in[1];
    const int*   lengths = (const int*)d_in[2];
    float* out = (float*)d_out;

    main_kernel<<<GRID, NT>>>(pred, truth, lengths, out, out_size);
}